// round 12
// baseline (speedup 1.0000x reference)
#include <cuda_runtime.h>
#include <cstddef>

#define TPB 256
#define WPB 8
#define MAX_PART 512
#define MAX_B 16
#define MAX_M 64

__device__ float4 g_part[MAX_B * MAX_PART];
__device__ unsigned int g_done = 0;

__device__ __forceinline__ float sl1f(float d) {
    return d < 1.f ? 0.5f * d * d : d - 0.5f;
}

// Deterministic final combine (fixed-order sums), run by last-done block.
__device__ void final_tail(float* __restrict__ out, int B, int nPart,
                           int out_size)
{
    __shared__ float4 s_acc[MAX_B];
    const int tid = threadIdx.x, w = tid >> 5, lane = tid & 31;
    for (int b = w; b < B; b += WPB) {
        float a0 = 0.f, a1 = 0.f, a2 = 0.f, a3 = 0.f;
        for (int i = lane; i < nPart; i += 32) {
            float4 v = g_part[b * MAX_PART + i];
            a0 += v.x; a1 += v.y; a2 += v.z; a3 += v.w;
        }
        #pragma unroll
        for (int off = 16; off; off >>= 1) {
            a0 += __shfl_down_sync(0xffffffffu, a0, off);
            a1 += __shfl_down_sync(0xffffffffu, a1, off);
            a2 += __shfl_down_sync(0xffffffffu, a2, off);
            a3 += __shfl_down_sync(0xffffffffu, a3, off);
        }
        if (lane == 0) s_acc[b] = make_float4(a0, a1, a2, a3);
    }
    __syncthreads();
    if (tid == 0) {
        const float K = -0.75f * 0.69314718055994531f;  // log2 -> ref domain
        float clsm = 0.f, es = 0.f, ec = 0.f;
        for (int b = 0; b < B; b++) {
            float4 v = s_acc[b];
            float cnt = v.w;
            float denom = fmaxf(cnt, 1.f);
            clsm += (K * v.x + v.y) / denom;
            if (cnt > 0.f) {
                float rm = v.z / (denom * 4.f);
                es += rm / denom + rm;
                ec += 2.f;
            } else ec += 1.f;
        }
        if (out_size >= 1) out[0] = clsm / (float)B;
        if (out_size >= 2) out[1] = es / ec;
    }
}

// ---------------------------------------------------------------------------
// Specialized kernel: M=32, C=80, B=8. One warp owns a 32-anchor tile for ALL
// batches: one conservative screen loop shared across batches; exact per-batch
// IoU only for screened-hot tiles; clampless coalesced focal stream.
// ---------------------------------------------------------------------------
__global__ void __launch_bounds__(TPB)
fused_kernel_spec(const float* __restrict__ cls,
                  const float* __restrict__ rgr,
                  const float* __restrict__ anchors,
                  const float* __restrict__ ann,
                  float* __restrict__ out,
                  int N, int out_size)
{
    constexpr int M = 32, C4 = 20, B = 8;
    const int tid = threadIdx.x, lane = tid & 31, wid = tid >> 5;

    __shared__ float4 s_box[B][M];
    __shared__ float2 s_ac [B][M];      // (area_b, class_id)
    __shared__ float4 s_scr[M];         // union-inflated corners
    __shared__ float  s_sab[M];         // min area_b over batches
    __shared__ float4 s_w[WPB][B];      // per-warp per-batch partials
    __shared__ bool   s_last;

    {   // load all batches' boxes: one (b, m) per thread (B*M = 256)
        int b = tid >> 5, m = tid & 31;
        const float* a = ann + ((size_t)b * M + m) * 5;
        float x1 = a[0], y1 = a[1], x2 = a[2], y2 = a[3];
        s_box[b][m] = make_float4(x1, y1, x2, y2);
        s_ac [b][m] = make_float2((x2 - x1) * (y2 - y1), a[4]);
    }
    if (lane < B) s_w[wid][lane] = make_float4(0.f, 0.f, 0.f, 0.f);
    __syncthreads();
    if (tid < M) {   // screen boxes (conservative: contains every batch box)
        float4 u = s_box[0][tid];
        float ab = s_ac[0][tid].x;
        #pragma unroll
        for (int b = 1; b < B; b++) {
            float4 v = s_box[b][tid];
            u.x = fminf(u.x, v.x); u.y = fminf(u.y, v.y);
            u.z = fmaxf(u.z, v.z); u.w = fmaxf(u.w, v.w);
            ab  = fminf(ab, s_ac[b][tid].x);
        }
        s_scr[tid] = u;
        s_sab[tid] = ab;
    }
    __syncthreads();

    const int tiles = (N + 31) / 32;
    for (int tile = blockIdx.x * WPB + wid; tile < tiles;
         tile += gridDim.x * WPB)
    {
        const int tb = tile * 32;
        const int n  = tb + lane;
        const bool fullTile = (tb + 32 <= N);
        const bool valid = (n < N);

        float cx = 0.f, cy = 0.f, aw = 1.f, ah = 1.f;
        float ax1 = 0.f, ay1 = 0.f, ax2 = -2.f, ay2 = -2.f, area_a = 3.0e38f;
        if (valid) {
            const float4 anc = __ldg((const float4*)(anchors + (size_t)n * 4));
            cx = anc.x; cy = anc.y; aw = anc.z; ah = anc.w;
            ax1 = cx - aw * 0.5f; ay1 = cy - ah * 0.5f;
            ax2 = cx + aw * 0.5f; ay2 = cy + ah * 0.5f;
            area_a = (ax2 - ax1) * (ay2 - ay1);
        }

        // ---- screen pass (ONCE for all batches): monotone-fp upper bound
        // on every batch's  max_m fmaf(3.0|3.5, inter, -area_b)
        float scr = -3.4e38f;
        #pragma unroll
        for (int m = 0; m < M; m++) {
            float4 bb = s_scr[m];
            float ix = fminf(ax2, bb.z) - fmaxf(ax1, bb.x);
            float iy = fminf(ay2, bb.w) - fmaxf(ay1, bb.y);
            float inter = fmaxf(ix, 0.f) * fmaxf(iy, 0.f);
            scr = fmaxf(scr, fmaf(3.5f, inter, -s_sab[m]));
        }
        const bool anyhot = __any_sync(0xffffffffu, scr >= area_a);

        for (int b = 0; b < B; b++) {
            bool pos = false, ign = false;
            if (anyhot) {
                // exact per-batch: iou>=0.5 <=> 3*inter-ab >= area_a
                //                  iou> 0.4 <=> 3.5*inter-ab > area_a
                float m05 = -3.4e38f, m04 = -3.4e38f;
                #pragma unroll
                for (int m = 0; m < M; m++) {
                    float4 bb = s_box[b][m];
                    float ab = s_ac[b][m].x;
                    float ix = fminf(ax2, bb.z) - fmaxf(ax1, bb.x);
                    float iy = fminf(ay2, bb.w) - fmaxf(ay1, bb.y);
                    float inter = fmaxf(ix, 0.f) * fmaxf(iy, 0.f);
                    m05 = fmaxf(m05, fmaf(3.0f, inter, -ab));
                    m04 = fmaxf(m04, fmaf(3.5f, inter, -ab));
                }
                pos = valid && (m05 >= area_a);
                ign = valid && (m04 > area_a) && !pos;
            }
            const unsigned ignmask = __ballot_sync(0xffffffffu, ign);

            // ---- clampless coalesced focal stream: sum u^2*log2(1-u)
            const float4* row4 = (const float4*)cls + ((size_t)b * N + tb) * C4;
            float acc0 = 0.f, acc1 = 0.f, acc2 = 0.f, acc3 = 0.f;
            if (fullTile && ignmask == 0u) {
                #pragma unroll 5
                for (int k = 0; k < C4; k++) {
                    const float4 v = __ldg(row4 + k * 32 + lane);
                    acc0 = fmaf(v.x * v.x, __log2f(1.f - v.x), acc0);
                    acc1 = fmaf(v.y * v.y, __log2f(1.f - v.y), acc1);
                    acc2 = fmaf(v.z * v.z, __log2f(1.f - v.z), acc2);
                    acc3 = fmaf(v.w * v.w, __log2f(1.f - v.w), acc3);
                }
            } else {
                const float maskf = ign ? 0.f : 1.f;
                const int limit = fullTile ? 32 * C4 : (N - tb) * C4;
                for (int k = 0; k < C4; k++) {
                    const int f = k * 32 + lane;
                    float4 v = make_float4(0.f, 0.f, 0.f, 0.f);
                    if (f < limit) v = __ldg(row4 + f);
                    const float mk = __shfl_sync(0xffffffffu, maskf, f / C4);
                    float p;
                    p = (v.x * v.x) * __log2f(1.f - v.x);
                    p = fmaf(v.y * v.y, __log2f(1.f - v.y), p);
                    p = fmaf(v.z * v.z, __log2f(1.f - v.z), p);
                    p = fmaf(v.w * v.w, __log2f(1.f - v.w), p);
                    acc0 = fmaf(mk, p, acc0);
                }
            }
            float t_f = (acc0 + acc1) + (acc2 + acc3);

            // ---- rare path: positive anchors
            float t_c = 0.f, t_r = 0.f, t_n = 0.f;
            if (__any_sync(0xffffffffu, pos)) {
                if (pos) {
                    float bi = -1.f, bu = 1.f;
                    int bm = 0;
                    #pragma unroll
                    for (int m = 0; m < M; m++) {
                        float4 bb = s_box[b][m];
                        float ab = s_ac[b][m].x;
                        float ix = fminf(ax2, bb.z) - fmaxf(ax1, bb.x);
                        float iy = fminf(ay2, bb.w) - fmaxf(ay1, bb.y);
                        float inter = fmaxf(ix, 0.f) * fmaxf(iy, 0.f);
                        float uni = area_a + ab - inter;
                        if (inter * bu > bi * uni) { bi = inter; bu = uni; bm = m; }
                    }
                    float4 bb = s_box[b][bm];
                    int cid = (int)s_ac[b][bm].y;

                    // remove clampless bulk term for cid; add exact pos term
                    float u = cls[((size_t)b * N + n) * 80 + cid];
                    float negterm = 0.75f * u * u * (-log1pf(-u));
                    float uc = fminf(fmaxf(u, 1e-4f), 0.9999f);
                    float om = 1.f - uc;
                    t_c = 0.25f * om * om * (-logf(uc)) - negterm;
                    t_n = 1.f;

                    float dwb = bb.z - bb.x, dhb = bb.w - bb.y;
                    float dxb = bb.x + bb.z * 0.5f;   // reference's center quirk
                    float dyb = bb.y + bb.w * 0.5f;
                    float dx = (dxb - cx) / aw;
                    float dy = (dyb - cy) / ah;
                    float dw = logf(dwb / aw);
                    float dh = logf(dhb / ah);
                    const float4 rg = __ldg((const float4*)(rgr + ((size_t)b * N + n) * 4));
                    float d0 = fabsf(rg.x / 0.1f - dx / 0.1f);
                    float d1 = fabsf(rg.y / 0.1f - dy / 0.1f);
                    float d2 = fabsf(rg.z / 0.2f - dw / 0.2f);
                    float d3 = fabsf(rg.w / 0.2f - dh / 0.2f);
                    t_r = sl1f(d0) + sl1f(d1) + sl1f(d2) + sl1f(d3);
                }
                #pragma unroll
                for (int off = 16; off; off >>= 1) {
                    t_c += __shfl_down_sync(0xffffffffu, t_c, off);
                    t_r += __shfl_down_sync(0xffffffffu, t_r, off);
                    t_n += __shfl_down_sync(0xffffffffu, t_n, off);
                }
            }
            #pragma unroll
            for (int off = 16; off; off >>= 1)
                t_f += __shfl_down_sync(0xffffffffu, t_f, off);
            if (lane == 0) {
                float4 w = s_w[wid][b];
                s_w[wid][b] = make_float4(w.x + t_f, w.y + t_c,
                                          w.z + t_r, w.w + t_n);
            }
        }
    }

    __syncthreads();
    if (tid < B) {   // fixed-order combine over warps
        float4 v = make_float4(0.f, 0.f, 0.f, 0.f);
        #pragma unroll
        for (int w = 0; w < WPB; w++) {
            float4 y = s_w[w][tid];
            v.x += y.x; v.y += y.y; v.z += y.z; v.w += y.w;
        }
        g_part[tid * MAX_PART + blockIdx.x] = v;
        __threadfence();
    }
    __syncthreads();
    if (tid == 0) {
        unsigned old = atomicAdd(&g_done, 1u);
        s_last = (old == gridDim.x - 1u);
    }
    __syncthreads();
    if (s_last) {
        __threadfence();
        final_tail(out, B, gridDim.x, out_size);
        __syncthreads();
        if (tid == 0) g_done = 0;   // reset for graph replay
    }
}

// ---------------------------------------------------------------------------
// Generic fallback (proven R10 structure): per-batch grid.y, per-thread anchor.
// ---------------------------------------------------------------------------
__global__ void __launch_bounds__(TPB)
fused_kernel_gen(const float* __restrict__ cls,
                 const float* __restrict__ rgr,
                 const float* __restrict__ anchors,
                 const float* __restrict__ ann,
                 float* __restrict__ out,
                 int N, int B, int C, int M, int out_size)
{
    const int b = blockIdx.y, tid = threadIdx.x;
    const int Mr = (M < MAX_M) ? M : MAX_M;
    __shared__ float4 s_box[MAX_M];
    __shared__ float2 s_ac [MAX_M];
    __shared__ bool s_last;
    for (int m = tid; m < Mr; m += TPB) {
        const float* a = ann + ((size_t)b * M + m) * 5;
        float x1 = a[0], y1 = a[1], x2 = a[2], y2 = a[3];
        s_box[m] = make_float4(x1, y1, x2, y2);
        s_ac [m] = make_float2((x2 - x1) * (y2 - y1), a[4]);
    }
    __syncthreads();

    float t_f = 0.f, t_c = 0.f, t_r = 0.f, t_n = 0.f;
    for (int n = blockIdx.x * TPB + tid; n < N; n += gridDim.x * TPB) {
        const float4 anc = __ldg((const float4*)(anchors + (size_t)n * 4));
        const float cx = anc.x, cy = anc.y, aw = anc.z, ah = anc.w;
        const float ax1 = cx - aw * 0.5f, ay1 = cy - ah * 0.5f;
        const float ax2 = cx + aw * 0.5f, ay2 = cy + ah * 0.5f;
        const float area_a = (ax2 - ax1) * (ay2 - ay1);
        float m05 = -3.4e38f, m04 = -3.4e38f;
        for (int m = 0; m < Mr; m++) {
            float4 bb = s_box[m];
            float ab = s_ac[m].x;
            float ix = fminf(ax2, bb.z) - fmaxf(ax1, bb.x);
            float iy = fminf(ay2, bb.w) - fmaxf(ay1, bb.y);
            float inter = fmaxf(ix, 0.f) * fmaxf(iy, 0.f);
            m05 = fmaxf(m05, fmaf(3.0f, inter, -ab));
            m04 = fmaxf(m04, fmaf(3.5f, inter, -ab));
        }
        const bool pos = (m05 >= area_a);
        const float maskf = (pos || !(m04 > area_a)) ? 1.f : 0.f;
        float acc = 0.f;
        const float* row = cls + ((size_t)b * N + n) * C;
        for (int j = 0; j < C; j++) {
            float u = fminf(row[j], 0.9999f);
            acc = fmaf(u * u, __log2f(1.f - u), acc);
        }
        t_f += maskf * acc;
        if (pos) {
            float bi = -1.f, bu = 1.f; int bm = 0;
            for (int m = 0; m < Mr; m++) {
                float4 bb = s_box[m];
                float ab = s_ac[m].x;
                float ix = fminf(ax2, bb.z) - fmaxf(ax1, bb.x);
                float iy = fminf(ay2, bb.w) - fmaxf(ay1, bb.y);
                float inter = fmaxf(ix, 0.f) * fmaxf(iy, 0.f);
                float uni = area_a + ab - inter;
                if (inter * bu > bi * uni) { bi = inter; bu = uni; bm = m; }
            }
            float4 bb = s_box[bm];
            int cid = (int)s_ac[bm].y;
            float u = fminf(fmaxf(row[cid], 1e-4f), 0.9999f);
            float om = 1.f - u;
            t_c += 0.25f * om * om * (-logf(u)) - 0.75f * u * u * (-log1pf(-u));
            t_n += 1.f;
            float dwb = bb.z - bb.x, dhb = bb.w - bb.y;
            float dx = (bb.x + bb.z * 0.5f - cx) / aw;
            float dy = (bb.y + bb.w * 0.5f - cy) / ah;
            float dw = logf(dwb / aw), dh = logf(dhb / ah);
            const float4 rg = __ldg((const float4*)(rgr + ((size_t)b * N + n) * 4));
            t_r += sl1f(fabsf(rg.x / 0.1f - dx / 0.1f))
                 + sl1f(fabsf(rg.y / 0.1f - dy / 0.1f))
                 + sl1f(fabsf(rg.z / 0.2f - dw / 0.2f))
                 + sl1f(fabsf(rg.w / 0.2f - dh / 0.2f));
        }
    }

    const int lane = tid & 31, w = tid >> 5;
    #pragma unroll
    for (int off = 16; off; off >>= 1) {
        t_f += __shfl_down_sync(0xffffffffu, t_f, off);
        t_c += __shfl_down_sync(0xffffffffu, t_c, off);
        t_r += __shfl_down_sync(0xffffffffu, t_r, off);
        t_n += __shfl_down_sync(0xffffffffu, t_n, off);
    }
    __shared__ float4 s[WPB];
    if (lane == 0) s[w] = make_float4(t_f, t_c, t_r, t_n);
    __syncthreads();
    if (tid == 0) {
        float4 v = s[0];
        for (int i = 1; i < WPB; i++) {
            float4 y = s[i];
            v.x += y.x; v.y += y.y; v.z += y.z; v.w += y.w;
        }
        g_part[b * MAX_PART + blockIdx.x] = v;
        __threadfence();
        unsigned old = atomicAdd(&g_done, 1u);
        s_last = (old == gridDim.x * gridDim.y - 1u);
    }
    __syncthreads();
    if (s_last) {
        __threadfence();
        final_tail(out, B, gridDim.x, out_size);
        __syncthreads();
        if (tid == 0) g_done = 0;
    }
}

extern "C" void kernel_launch(void* const* d_in, const int* in_sizes, int n_in,
                              void* d_out, int out_size)
{
    int order[4] = {0, 1, 2, 3};
    for (int i = 0; i < 3; i++)
        for (int j = i + 1; j < 4; j++)
            if ((long long)in_sizes[order[j]] > (long long)in_sizes[order[i]]) {
                int t = order[i]; order[i] = order[j]; order[j] = t;
            }
    const float* cls     = (const float*)d_in[order[0]];
    const float* rgr     = (const float*)d_in[order[1]];
    const float* anchors = (const float*)d_in[order[2]];
    const float* ann     = (const float*)d_in[order[3]];

    const int N = in_sizes[order[2]] / 4;
    const int B = (int)(in_sizes[order[1]] / (4LL * N));
    const int C = (int)(in_sizes[order[0]] / ((long long)B * N));
    const int M = (int)(in_sizes[order[3]] / (5LL * B));

    if (M == 32 && C == 80 && B == 8) {
        const int tiles = (N + 31) / 32;
        int blocks = (tiles + WPB - 1) / WPB;
        if (blocks > MAX_PART) blocks = MAX_PART;
        fused_kernel_spec<<<blocks, TPB>>>(cls, rgr, anchors, ann,
                                           (float*)d_out, N, out_size);
    } else {
        int blocks = (N + TPB - 1) / TPB;
        if (blocks > MAX_PART) blocks = MAX_PART;
        dim3 grid(blocks, B);
        fused_kernel_gen<<<grid, TPB>>>(cls, rgr, anchors, ann,
                                        (float*)d_out, N, B, C, M, out_size);
    }
}